// round 2
// baseline (speedup 1.0000x reference)
#include <cuda_runtime.h>

#define NN    8192
#define KIN   512
#define OUTF  64
#define ALPHA 0.2f

typedef unsigned long long ull;

// ---------------- device scratch (no runtime allocation allowed) ----------------
__device__ float g_h[NN * OUTF];      // 2 MB
__device__ float g_attl[NN];
__device__ float g_attr[NN];
__device__ int   g_maxR;              // encoded float max of att_r

// ---------------- small helpers ----------------
__device__ __forceinline__ ull fma2(ull a, ull b, ull c) {
    ull d;
    asm("fma.rn.f32x2 %0, %1, %2, %3;" : "=l"(d) : "l"(a), "l"(b), "l"(c));
    return d;
}
__device__ __forceinline__ ull dup2(float v) {
    ull d;
    asm("mov.b64 %0, {%1, %1};" : "=l"(d) : "f"(v));
    return d;
}
__device__ __forceinline__ ull pack2(float x, float y) {
    ull d;
    asm("mov.b64 %0, {%1, %2};" : "=l"(d) : "f"(x), "f"(y));
    return d;
}
__device__ __forceinline__ void lds2x64(ull &a, ull &b, unsigned sa) {
    asm volatile("ld.shared.v2.b64 {%0, %1}, [%2];" : "=l"(a), "=l"(b) : "r"(sa));
}
__device__ __forceinline__ float lo32(ull a) {
    return __int_as_float((int)(unsigned)a);
}
__device__ __forceinline__ int enc_f(float f) {
    int i = __float_as_int(f);
    return (i >= 0) ? i : (i ^ 0x7fffffff);
}
__device__ __forceinline__ float dec_f(int i) {
    int j = (i >= 0) ? i : (i ^ 0x7fffffff);
    return __int_as_float(j);
}
union U64F2 { ull u; float2 f; };

// ---------------- kernel 0: reset global max (graph-replay safe) ----------------
__global__ void k_init() { g_maxR = (int)0x80000000; }

// ---------------- kernel 1: h = input @ W  (8192x512 @ 512x64) ----------------
__global__ __launch_bounds__(256) void k_gemm(const float* __restrict__ input,
                                              const float* __restrict__ W) {
    __shared__ float in_s[64][68];   // pad 68 -> 16B-aligned rows, conflict-free reads
    __shared__ float w_s[64][64];

    const int tid = threadIdx.x;
    const int i0 = blockIdx.x * 64;
    const int rg = tid >> 4;    // 16 row-groups * 4 rows
    const int cg = tid & 15;    // 16 col-groups * 4 cols

    ull acc[4][2];
#pragma unroll
    for (int r = 0; r < 4; r++) { acc[r][0] = 0ull; acc[r][1] = 0ull; }

    for (int kc = 0; kc < KIN; kc += 64) {
        __syncthreads();
#pragma unroll
        for (int m = 0; m < 4; m++) {
            int idx = tid + 256 * m;
            int r = idx >> 4, k4 = (idx & 15) * 4;
            *(float4*)&in_s[r][k4] = *(const float4*)&input[(i0 + r) * KIN + kc + k4];
        }
#pragma unroll
        for (int m = 0; m < 4; m++) {
            int idx = tid + 256 * m;
            int k = idx >> 4, c4 = (idx & 15) * 4;
            *(float4*)&w_s[k][c4] = *(const float4*)&W[(kc + k) * OUTF + c4];
        }
        __syncthreads();

#pragma unroll 8
        for (int k = 0; k < 64; k++) {
            float4 wv = *(float4*)&w_s[k][cg * 4];
            ull wp0 = pack2(wv.x, wv.y);
            ull wp1 = pack2(wv.z, wv.w);
#pragma unroll
            for (int rr = 0; rr < 4; rr++) {
                ull vd = dup2(in_s[rg * 4 + rr][k]);
                acc[rr][0] = fma2(vd, wp0, acc[rr][0]);
                acc[rr][1] = fma2(vd, wp1, acc[rr][1]);
            }
        }
    }

#pragma unroll
    for (int rr = 0; rr < 4; rr++) {
        U64F2 a0, a1; a0.u = acc[rr][0]; a1.u = acc[rr][1];
        *(float4*)&g_h[(i0 + rg * 4 + rr) * OUTF + cg * 4] =
            make_float4(a0.f.x, a0.f.y, a1.f.x, a1.f.y);
    }
}

// ---------------- kernel 2: att_l, att_r, global max(att_r) ----------------
__global__ __launch_bounds__(256) void k_att(const float* __restrict__ a) {
    const int w = threadIdx.x >> 5, lane = threadIdx.x & 31;
    const int row = blockIdx.x * 8 + w;
    float h0 = g_h[row * OUTF + lane];
    float h1 = g_h[row * OUTF + 32 + lane];
    float al = h0 * a[lane] + h1 * a[lane + 32];
    float ar = h0 * a[64 + lane] + h1 * a[96 + lane];
#pragma unroll
    for (int off = 16; off; off >>= 1) {
        al += __shfl_down_sync(0xffffffffu, al, off);
        ar += __shfl_down_sync(0xffffffffu, ar, off);
    }
    if (lane == 0) {
        g_attl[row] = al;
        g_attr[row] = ar;
        atomicMax(&g_maxR, enc_f(ar));
    }
}

// ---------------- kernel 3: fused masked-softmax-weighted aggregation + ELU ----
// smem layout (bytes):
//   [0, 32768)        h_s      : 128 x 64 floats (j-tile of h)
//   [32768, 98304)    w2_s     : 64 x 128 float2 (duplicated weight pairs)
//   [98304, 98816)    ar_s     : 128 floats
//   [98816, 99072)    al_s     : 64 floats
//   [99072, 99328)    C_s      : 64 floats
//   [99328, 99584)    Z_s      : 64 floats
#define SM_HS  0
#define SM_W2  32768
#define SM_AR  98304
#define SM_AL  98816
#define SM_CS  99072
#define SM_ZS  99328
#define SM_TOT 99584

__global__ __launch_bounds__(256, 1) void k_fused(const int* __restrict__ adj,
                                                  float* __restrict__ out) {
    extern __shared__ char smem[];
    const unsigned sbase = (unsigned)__cvta_generic_to_shared(smem);
    const int tid = threadIdx.x;
    const int i0 = blockIdx.x * 64;
    const int ig = tid >> 4;   // 16 groups * 4 rows
    const int cg = tid & 15;   // 16 groups * 4 cols

    // per-row shift C_i = lrelu(att_l[i] + maxR)
    if (tid < 64) {
        float al = g_attl[i0 + tid];
        float mr = dec_f(g_maxR);
        float s = al + mr;
        ((float*)(smem + SM_AL))[tid] = al;
        ((float*)(smem + SM_CS))[tid] = fmaxf(s, ALPHA * s);
    }

    ull acc[4][2];
#pragma unroll
    for (int r = 0; r < 4; r++) { acc[r][0] = 0ull; acc[r][1] = 0ull; }
    float Zr[4] = {0.f, 0.f, 0.f, 0.f};

    const unsigned wbase = sbase + SM_W2 + (unsigned)(ig * 4) * 128u * 8u;
    const unsigned hbase = sbase + SM_HS + (unsigned)cg * 16u;

    for (int jt = 0; jt < NN / 128; jt++) {
        const int j0 = jt * 128;
        __syncthreads();   // protect smem tiles from previous iteration

        // load h tile (contiguous 32KB) and att_r tile
        {
            const float4* hsrc = (const float4*)&g_h[j0 * OUTF];
            float4* hdst = (float4*)(smem + SM_HS);
#pragma unroll
            for (int m = 0; m < 8; m++) hdst[tid + 256 * m] = hsrc[tid + 256 * m];
            if (tid < 128) ((float*)(smem + SM_AR))[tid] = g_attr[j0 + tid];
        }
        __syncthreads();

        // ---- phase A: weight tile w[i][j] = adj ? exp(lrelu(al+ar) - C_i) : 0,
        //      stored duplicated as (w,w) pairs for FFMA2 phase ----
        {
            const int jj4 = (tid & 31) * 4;
            float4 arv = *(float4*)(smem + SM_AR + jj4 * 4);
#pragma unroll
            for (int it = 0; it < 8; it++) {
                int r = (tid >> 5) + it * 8;
                int4 adj4 = *(const int4*)&adj[(i0 + r) * NN + j0 + jj4];
                float al = ((float*)(smem + SM_AL))[r];
                float C  = ((float*)(smem + SM_CS))[r];
                float s0 = al + arv.x, s1 = al + arv.y, s2 = al + arv.z, s3 = al + arv.w;
                float e0 = fmaxf(s0, ALPHA * s0), e1 = fmaxf(s1, ALPHA * s1);
                float e2 = fmaxf(s2, ALPHA * s2), e3 = fmaxf(s3, ALPHA * s3);
                float w0 = adj4.x ? __expf(e0 - C) : 0.f;
                float w1 = adj4.y ? __expf(e1 - C) : 0.f;
                float w2 = adj4.z ? __expf(e2 - C) : 0.f;
                float w3 = adj4.w ? __expf(e3 - C) : 0.f;
                float4* wd = (float4*)(smem + SM_W2 + (r * 128 + jj4) * 8);
                wd[0] = make_float4(w0, w0, w1, w1);
                wd[1] = make_float4(w2, w2, w3, w3);
            }
        }
        __syncthreads();

        // ---- phase B: acc[64x64] += w[64x128] @ h[128x64] via FFMA2 ----
#pragma unroll 2
        for (int j = 0; j < 128; j += 2) {
            ull wp[4][2], hp[2][2];
#pragma unroll
            for (int r = 0; r < 4; r++)
                lds2x64(wp[r][0], wp[r][1], wbase + (unsigned)(r * 1024 + j * 8));
            lds2x64(hp[0][0], hp[0][1], hbase + (unsigned)(j * 256));
            lds2x64(hp[1][0], hp[1][1], hbase + (unsigned)((j + 1) * 256));
#pragma unroll
            for (int r = 0; r < 4; r++) {
                acc[r][0] = fma2(wp[r][0], hp[0][0], acc[r][0]);
                acc[r][1] = fma2(wp[r][0], hp[0][1], acc[r][1]);
                acc[r][0] = fma2(wp[r][1], hp[1][0], acc[r][0]);
                acc[r][1] = fma2(wp[r][1], hp[1][1], acc[r][1]);
            }
            if (cg == 0) {
#pragma unroll
                for (int r = 0; r < 4; r++)
                    Zr[r] += lo32(wp[r][0]) + lo32(wp[r][1]);
            }
        }
    }

    // ---- normalize + ELU + store ----
    __syncthreads();
    if (cg == 0) {
#pragma unroll
        for (int r = 0; r < 4; r++)
            ((float*)(smem + SM_ZS))[ig * 4 + r] = Zr[r];
    }
    __syncthreads();

#pragma unroll
    for (int r = 0; r < 4; r++) {
        float z = ((float*)(smem + SM_ZS))[ig * 4 + r];
        float inv = 1.0f / z;
        U64F2 a0, a1; a0.u = acc[r][0]; a1.u = acc[r][1];
        float v0 = a0.f.x * inv, v1 = a0.f.y * inv;
        float v2 = a1.f.x * inv, v3 = a1.f.y * inv;
        v0 = (v0 > 0.f) ? v0 : expm1f(v0);
        v1 = (v1 > 0.f) ? v1 : expm1f(v1);
        v2 = (v2 > 0.f) ? v2 : expm1f(v2);
        v3 = (v3 > 0.f) ? v3 : expm1f(v3);
        *(float4*)&out[(i0 + ig * 4 + r) * OUTF + cg * 4] = make_float4(v0, v1, v2, v3);
    }
}

// ---------------- launch ----------------
extern "C" void kernel_launch(void* const* d_in, const int* in_sizes, int n_in,
                              void* d_out, int out_size) {
    const float* input = (const float*)d_in[0];   // [8192, 512] f32
    const int*   adj   = (const int*)d_in[1];     // [8192, 8192] i32
    const float* W     = (const float*)d_in[2];   // [512, 64] f32
    const float* a     = (const float*)d_in[3];   // [128, 1] f32
    float* out = (float*)d_out;                   // [8192, 64] f32

    cudaFuncSetAttribute(k_fused, cudaFuncAttributeMaxDynamicSharedMemorySize, SM_TOT);

    k_init<<<1, 1>>>();
    k_gemm<<<NN / 64, 256>>>(input, W);
    k_att<<<NN / 8, 256>>>(a);
    k_fused<<<NN / 64, 256, SM_TOT>>>(adj, out);
}